// round 8
// baseline (speedup 1.0000x reference)
#include <cuda_runtime.h>
#include <cuda_bf16.h>

#define NQ 8
#define NL 4
#define BATCHN 4096
#define FULLMASK 0xffffffffu

// ---------------- f32x2 packed math helpers ----------------
__device__ __forceinline__ float2 f2fma(float2 a, float2 b, float2 c) {
    float2 d;
    asm("{\n\t"
        ".reg .b64 ra, rb, rc, rd;\n\t"
        "mov.b64 ra, {%2,%3};\n\t"
        "mov.b64 rb, {%4,%5};\n\t"
        "mov.b64 rc, {%6,%7};\n\t"
        "fma.rn.f32x2 rd, ra, rb, rc;\n\t"
        "mov.b64 {%0,%1}, rd;\n\t"
        "}"
        : "=f"(d.x), "=f"(d.y)
        : "f"(a.x), "f"(a.y), "f"(b.x), "f"(b.y), "f"(c.x), "f"(c.y));
    return d;
}
__device__ __forceinline__ float2 f2mul(float2 a, float2 b) {
    float2 d;
    asm("{\n\t"
        ".reg .b64 ra, rb, rd;\n\t"
        "mov.b64 ra, {%2,%3};\n\t"
        "mov.b64 rb, {%4,%5};\n\t"
        "mul.rn.f32x2 rd, ra, rb;\n\t"
        "mov.b64 {%0,%1}, rd;\n\t"
        "}"
        : "=f"(d.x), "=f"(d.y)
        : "f"(a.x), "f"(a.y), "f"(b.x), "f"(b.y));
    return d;
}
__device__ __forceinline__ float2 shflx2(float2 v, int m) {
    v.x = __shfl_xor_sync(FULLMASK, v.x, m);
    v.y = __shfl_xor_sync(FULLMASK, v.y, m);
    return v;
}

// State layout: ONE sample per warp. 8 amplitudes per lane packed as float2
// PR[4]/PI[4]; amplitude index = lane*8 + 2k + h (h = .x/.y half).
// Qubit q <-> index bit (7-q):
//   q0->lane b4, q1->lane b3, q2->lane b2, q3->lane b1, q4->lane b0,
//   q5->k b1,    q6->k b0,    q7->packed half h.

// RY on a k-bit (q5: ks=2, q6: ks=1)
__device__ __forceinline__ void ry_reg(float2* PR, float2* PI, float c, float s, int ks) {
    float2 c2 = make_float2(c, c), s2 = make_float2(s, s), n2 = make_float2(-s, -s);
#pragma unroll
    for (int k = 0; k < 4; k++) if (!(k & ks)) {
        const int k2 = k | ks;
        float2 r0 = PR[k], r1 = PR[k2], i0 = PI[k], i1 = PI[k2];
        PR[k]  = f2fma(n2, r1, f2mul(c2, r0));
        PR[k2] = f2fma(s2, r0, f2mul(c2, r1));
        PI[k]  = f2fma(n2, i1, f2mul(c2, i0));
        PI[k2] = f2fma(s2, i0, f2mul(c2, i1));
    }
}
// RY on q7 (packed halves)
__device__ __forceinline__ void ry_pk(float2* PR, float2* PI, float c, float s) {
    float2 c2 = make_float2(c, c), sn = make_float2(-s, s);
#pragma unroll
    for (int k = 0; k < 4; k++) {
        float2 r = PR[k], i = PI[k];
        PR[k] = f2fma(sn, make_float2(r.y, r.x), f2mul(c2, r));
        PI[k] = f2fma(sn, make_float2(i.y, i.x), f2mul(c2, i));
    }
}
// RY on a lane bit (q0..q4)
__device__ __forceinline__ void ry_ln(float2* PR, float2* PI, float c, float s, int lb, int lane) {
    const float ss = (lane & lb) ? s : -s;
    float2 c2 = make_float2(c, c), s2 = make_float2(ss, ss);
#pragma unroll
    for (int k = 0; k < 4; k++) {
        float2 pr = shflx2(PR[k], lb);
        float2 pi = shflx2(PI[k], lb);
        PR[k] = f2fma(s2, pr, f2mul(c2, PR[k]));
        PI[k] = f2fma(s2, pi, f2mul(c2, PI[k]));
    }
}
// RZ on q7 (sign differs inside the pair -> single packed constant)
__device__ __forceinline__ void rz_pk(float2* PR, float2* PI, float c, float s) {
    float2 c2 = make_float2(c, c), sg = make_float2(-s, s), ng = make_float2(s, -s);
#pragma unroll
    for (int k = 0; k < 4; k++) {
        float2 r = PR[k], i = PI[k];
        PR[k] = f2fma(ng, i, f2mul(c2, r));
        PI[k] = f2fma(sg, r, f2mul(c2, i));
    }
}
// RZ on a k-bit
__device__ __forceinline__ void rz_reg(float2* PR, float2* PI, float c, float s, int ks) {
    float2 c2 = make_float2(c, c), sp = make_float2(s, s), sm = make_float2(-s, -s);
#pragma unroll
    for (int k = 0; k < 4; k++) {
        float2 sg = (k & ks) ? sp : sm;
        float2 ng = (k & ks) ? sm : sp;
        float2 r = PR[k], i = PI[k];
        PR[k] = f2fma(ng, i, f2mul(c2, r));
        PI[k] = f2fma(sg, r, f2mul(c2, i));
    }
}
// RZ on a lane bit
__device__ __forceinline__ void rz_ln(float2* PR, float2* PI, float c, float s, int lb, int lane) {
    const float g = (lane & lb) ? s : -s;
    float2 c2 = make_float2(c, c), g2 = make_float2(g, g), n2 = make_float2(-g, -g);
#pragma unroll
    for (int k = 0; k < 4; k++) {
        float2 r = PR[k], i = PI[k];
        PR[k] = f2fma(n2, i, f2mul(c2, r));
        PI[k] = f2fma(g2, r, f2mul(c2, i));
    }
}

// CNOT ring: control q_i -> target q_{i+1}, i = 0..7 in order.
__device__ __forceinline__ void cnot_ring(float2* PR, float2* PI, int lane, int src0123) {
    // i=0..3 composed (all on lane bits b4..b1 -> b3..b0): one index shuffle
#pragma unroll
    for (int k = 0; k < 4; k++) {
        PR[k].x = __shfl_sync(FULLMASK, PR[k].x, src0123);
        PR[k].y = __shfl_sync(FULLMASK, PR[k].y, src0123);
        PI[k].x = __shfl_sync(FULLMASK, PI[k].x, src0123);
        PI[k].y = __shfl_sync(FULLMASK, PI[k].y, src0123);
    }
    // i=4: c=q4 (lane b0), t=q5 (k b1): swap k<->k+2 where control set
    if (lane & 1) {
        float2 t = PR[0]; PR[0] = PR[2]; PR[2] = t;
        t = PI[0]; PI[0] = PI[2]; PI[2] = t;
        t = PR[1]; PR[1] = PR[3]; PR[3] = t;
        t = PI[1]; PI[1] = PI[3]; PI[3] = t;
    }
    // i=5: c=q5 (k b1), t=q6 (k b0): swap k=2<->3
    {
        float2 t = PR[2]; PR[2] = PR[3]; PR[3] = t;
        t = PI[2]; PI[2] = PI[3]; PI[3] = t;
    }
    // i=6: c=q6 (k b0), t=q7 (half): swap halves for odd k
#pragma unroll
    for (int k = 1; k < 4; k += 2) {
        PR[k] = make_float2(PR[k].y, PR[k].x);
        PI[k] = make_float2(PI[k].y, PI[k].x);
    }
    // i=7: c=q7 (odd half .y), t=q0 (lane b4): only .y moves
#pragma unroll
    for (int k = 0; k < 4; k++) {
        PR[k].y = __shfl_xor_sync(FULLMASK, PR[k].y, 16);
        PI[k].y = __shfl_xor_sync(FULLMASK, PI[k].y, 16);
    }
}

__global__ __launch_bounds__(256) void vqc_kernel(
    const float* __restrict__ x,      // (4096, 8)
    const float* __restrict__ w,      // (4, 8, 2)
    float* __restrict__ out)          // (4096,)
{
    __shared__ float wc[NL * NQ * 2];
    __shared__ float ws[NL * NQ * 2];
    const int tid = threadIdx.x;
    if (tid < NL * NQ * 2) {
        float a = 0.5f * w[tid];
        float s, c;
        sincosf(a, &s, &c);
        wc[tid] = c; ws[tid] = s;
    }
    __syncthreads();

    const int lane = tid & 31;
    const int sample = blockIdx.x * 8 + (tid >> 5);   // one sample per warp

    // Composed inverse lane permutation for ring CNOTs i=0..3 (lane bits):
    // forward: b3^=b4; b2^=b3'; b1^=b2'; b0^=b1'
    // inverse: s4=d4, s3=d3^d4, s2=d2^d3, s1=d1^d2, s0=d0^d1
    const int b4 = (lane >> 4) & 1, b3 = (lane >> 3) & 1, b2 = (lane >> 2) & 1,
              b1 = (lane >> 1) & 1, b0 = lane & 1;
    const int src0123 = (b4 << 4) | ((b3 ^ b4) << 3) | ((b2 ^ b3) << 2) |
                        ((b1 ^ b2) << 1) | (b0 ^ b1);

    // ---------- Angle encoding as direct product state (all-real) ----------
    float cq[8], sq[8];
    {
        const float4* xv = (const float4*)(x + sample * NQ);
        float4 xa = __ldg(xv), xb = __ldg(xv + 1);
        float xs[8] = {xa.x, xa.y, xa.z, xa.w, xb.x, xb.y, xb.z, xb.w};
#pragma unroll
        for (int q = 0; q < 8; q++) __sincosf(0.5f * xs[q], &sq[q], &cq[q]);
    }
    // lane factor: q0..q4 from lane bits b4..b0
    float A = (b4 ? sq[0] : cq[0]) * (b3 ? sq[1] : cq[1]) * (b2 ? sq[2] : cq[2]) *
              (b1 ? sq[3] : cq[3]) * (b0 ? sq[4] : cq[4]);
    float u2[2], u4[4];
    u2[0] = A * cq[5];  u2[1] = A * sq[5];                       // k b1 = q5
#pragma unroll
    for (int k = 0; k < 4; k++) u4[k] = u2[k >> 1] * ((k & 1) ? sq[6] : cq[6]);

    float2 PR[4], PI[4];
#pragma unroll
    for (int k = 0; k < 4; k++) {
        PR[k] = make_float2(u4[k] * cq[7], u4[k] * sq[7]);       // half = q7
        PI[k] = make_float2(0.0f, 0.0f);
    }

    // ---------------- Layers 0..2: full ring + all rotations ----------------
#pragma unroll 1
    for (int l = 0; l < NL - 1; l++) {
        cnot_ring(PR, PI, lane, src0123);
        const int lbase = l * 16;
#pragma unroll
        for (int i = 0; i < NQ; i++) {
            const int base = lbase + i * 2;
            const float cy = wc[base],     sy = ws[base];
            const float cz = wc[base + 1], sz = ws[base + 1];
            if (i < 5) {
                const int lb = 16 >> i;
                ry_ln(PR, PI, cy, sy, lb, lane);
                rz_ln(PR, PI, cz, sz, lb, lane);
            } else if (i == 7) {
                ry_pk(PR, PI, cy, sy);
                rz_pk(PR, PI, cz, sz);
            } else {
                const int ks = 1 << (6 - i);   // q5 -> 2, q6 -> 1
                ry_reg(PR, PI, cy, sy, ks);
                rz_reg(PR, PI, cz, sz, ks);
            }
        }
    }

    // ---------------- Layer 3: ring + RY(q0) only ----------------
    // Final-layer rotations on qubits != q0 preserve the q0 marginal; the
    // diagonal RZ(q0) preserves |amp|^2 -> no effect on <Z_0>.
    cnot_ring(PR, PI, lane, src0123);
    {
        const int base = 3 * 16;  // (l=3, i=0, RY)
        ry_ln(PR, PI, wc[base], ws[base], 16, lane);
    }

    // ---------------- <Z_0>: q0 = lane bit4 ----------------
    float2 a2 = make_float2(0.0f, 0.0f);
#pragma unroll
    for (int k = 0; k < 4; k++) {
        a2 = f2fma(PR[k], PR[k], a2);
        a2 = f2fma(PI[k], PI[k], a2);
    }
    float acc = a2.x + a2.y;
    if (lane & 16) acc = -acc;
    acc += __shfl_xor_sync(FULLMASK, acc, 1);
    acc += __shfl_xor_sync(FULLMASK, acc, 2);
    acc += __shfl_xor_sync(FULLMASK, acc, 4);
    acc += __shfl_xor_sync(FULLMASK, acc, 8);
    acc += __shfl_xor_sync(FULLMASK, acc, 16);
    if (lane == 0) out[sample] = acc;
}

extern "C" void kernel_launch(void* const* d_in, const int* in_sizes, int n_in,
                              void* d_out, int out_size) {
    const float* x = (const float*)d_in[0];   // (4096, 8)
    const float* w = (const float*)d_in[1];   // (4, 8, 2)
    float* out = (float*)d_out;               // (4096,)
    // 256 threads = 8 warps = 8 samples per block; 512 blocks, 4096 warps
    vqc_kernel<<<BATCHN / 8, 256>>>(x, w, out);
}

// round 9
// speedup vs baseline: 1.1593x; 1.1593x over previous
#include <cuda_runtime.h>
#include <cuda_bf16.h>

#define NQ 8
#define NL 4
#define BATCHN 4096
#define FULLMASK 0xffffffffu

// ---------------- f32x2 packed math helpers ----------------
__device__ __forceinline__ float2 f2fma(float2 a, float2 b, float2 c) {
    float2 d;
    asm("{\n\t"
        ".reg .b64 ra, rb, rc, rd;\n\t"
        "mov.b64 ra, {%2,%3};\n\t"
        "mov.b64 rb, {%4,%5};\n\t"
        "mov.b64 rc, {%6,%7};\n\t"
        "fma.rn.f32x2 rd, ra, rb, rc;\n\t"
        "mov.b64 {%0,%1}, rd;\n\t"
        "}"
        : "=f"(d.x), "=f"(d.y)
        : "f"(a.x), "f"(a.y), "f"(b.x), "f"(b.y), "f"(c.x), "f"(c.y));
    return d;
}
__device__ __forceinline__ float2 shflx2(float2 v, int m) {
    v.x = __shfl_xor_sync(FULLMASK, v.x, m);
    v.y = __shfl_xor_sync(FULLMASK, v.y, m);
    return v;
}

// State layout: ONE sample per warp. 8 amplitudes per lane packed as float2
// PR[4]/PI[4]; amplitude index = lane*8 + 2k + h (h = .x/.y half).
// Qubit q <-> index bit (7-q):
//   q0->lane b4, q1->lane b3, q2->lane b2, q3->lane b1, q4->lane b0,
//   q5->k b1,    q6->k b0,    q7->packed half h.
//
// All variational rotations are applied in TANGENT form (gate / cos(theta/2));
// the product of the dropped cosines is applied once as C^2 on <Z_0>.

// RY(tan form) on a k-bit (q5: ks=2, q6: ks=1): a0 -= t*a1; a1 += t*a0_old
__device__ __forceinline__ void ry_reg_t(float2* PR, float2* PI, float t, int ks) {
    float2 tp = make_float2(t, t), tn = make_float2(-t, -t);
#pragma unroll
    for (int k = 0; k < 4; k++) if (!(k & ks)) {
        const int k2 = k | ks;
        float2 r0 = PR[k], i0 = PI[k];
        PR[k]  = f2fma(tn, PR[k2], r0);
        PR[k2] = f2fma(tp, r0, PR[k2]);
        PI[k]  = f2fma(tn, PI[k2], i0);
        PI[k2] = f2fma(tp, i0, PI[k2]);
    }
}
// RY(tan form) on q7 (packed halves)
__device__ __forceinline__ void ry_pk_t(float2* PR, float2* PI, float t) {
    float2 ts = make_float2(-t, t);
#pragma unroll
    for (int k = 0; k < 4; k++) {
        float2 r = PR[k], i = PI[k];
        PR[k] = f2fma(ts, make_float2(r.y, r.x), r);
        PI[k] = f2fma(ts, make_float2(i.y, i.x), i);
    }
}
// RY(tan form) on a lane bit (q0..q4)
__device__ __forceinline__ void ry_ln_t(float2* PR, float2* PI, float t, int lb, int lane) {
    const float ss = (lane & lb) ? t : -t;
    float2 t2 = make_float2(ss, ss);
#pragma unroll
    for (int k = 0; k < 4; k++) {
        float2 pr = shflx2(PR[k], lb);
        float2 pi = shflx2(PI[k], lb);
        PR[k] = f2fma(t2, pr, PR[k]);
        PI[k] = f2fma(t2, pi, PI[k]);
    }
}
// RZ(tan form) on q7: bit=0 -> r += t*im, im -= t*r ; bit=1 -> conj
__device__ __forceinline__ void rz_pk_t(float2* PR, float2* PI, float t) {
    float2 tp = make_float2(t, -t), tn = make_float2(-t, t);
#pragma unroll
    for (int k = 0; k < 4; k++) {
        float2 r = PR[k];
        PR[k] = f2fma(tp, PI[k], r);
        PI[k] = f2fma(tn, r, PI[k]);
    }
}
// RZ(tan form) on a k-bit
__device__ __forceinline__ void rz_reg_t(float2* PR, float2* PI, float t, int ks) {
    float2 tp = make_float2(t, t), tn = make_float2(-t, -t);
#pragma unroll
    for (int k = 0; k < 4; k++) {
        float2 a = (k & ks) ? tn : tp;     // coef on PI into PR
        float2 b = (k & ks) ? tp : tn;     // coef on PR into PI
        float2 r = PR[k];
        PR[k] = f2fma(a, PI[k], r);
        PI[k] = f2fma(b, r, PI[k]);
    }
}
// RZ(tan form) on a lane bit
__device__ __forceinline__ void rz_ln_t(float2* PR, float2* PI, float t, int lb, int lane) {
    const float g = (lane & lb) ? -t : t;
    float2 a = make_float2(g, g), b = make_float2(-g, -g);
#pragma unroll
    for (int k = 0; k < 4; k++) {
        float2 r = PR[k];
        PR[k] = f2fma(a, PI[k], r);
        PI[k] = f2fma(b, r, PI[k]);
    }
}

// CNOT ring: control q_i -> target q_{i+1}, i = 0..7 in order.
__device__ __forceinline__ void cnot_ring(float2* PR, float2* PI, int lane, int src0123) {
    // i=0..3 composed (all on lane bits): one index shuffle
#pragma unroll
    for (int k = 0; k < 4; k++) {
        PR[k].x = __shfl_sync(FULLMASK, PR[k].x, src0123);
        PR[k].y = __shfl_sync(FULLMASK, PR[k].y, src0123);
        PI[k].x = __shfl_sync(FULLMASK, PI[k].x, src0123);
        PI[k].y = __shfl_sync(FULLMASK, PI[k].y, src0123);
    }
    // i=4: c=q4 (lane b0), t=q5 (k b1): swap k<->k+2 where control set
    if (lane & 1) {
        float2 t = PR[0]; PR[0] = PR[2]; PR[2] = t;
        t = PI[0]; PI[0] = PI[2]; PI[2] = t;
        t = PR[1]; PR[1] = PR[3]; PR[3] = t;
        t = PI[1]; PI[1] = PI[3]; PI[3] = t;
    }
    // i=5: c=q5 (k b1), t=q6 (k b0): swap k=2<->3
    {
        float2 t = PR[2]; PR[2] = PR[3]; PR[3] = t;
        t = PI[2]; PI[2] = PI[3]; PI[3] = t;
    }
    // i=6: c=q6 (k b0), t=q7 (half): swap halves for odd k
#pragma unroll
    for (int k = 1; k < 4; k += 2) {
        PR[k] = make_float2(PR[k].y, PR[k].x);
        PI[k] = make_float2(PI[k].y, PI[k].x);
    }
    // i=7: c=q7 (odd half .y), t=q0 (lane b4): only .y moves
#pragma unroll
    for (int k = 0; k < 4; k++) {
        PR[k].y = __shfl_xor_sync(FULLMASK, PR[k].y, 16);
        PI[k].y = __shfl_xor_sync(FULLMASK, PI[k].y, 16);
    }
}

__global__ __launch_bounds__(256) void vqc_kernel(
    const float* __restrict__ x,      // (4096, 8)
    const float* __restrict__ w,      // (4, 8, 2)
    float* __restrict__ out)          // (4096,)
{
    __shared__ float wt[NL * NQ * 2];   // tan(w/2)
    __shared__ float wcs[NL * NQ * 2];  // cos(w/2)
    __shared__ float scale2;            // (prod of applied cos)^2
    const int tid = threadIdx.x;
    if (tid < NL * NQ * 2) {
        float a = 0.5f * w[tid];
        float s, c;
        sincosf(a, &s, &c);
        wt[tid]  = __fdividef(s, c);
        wcs[tid] = c;
    }
    __syncthreads();
    if (tid == 0) {
        // applied gates: layers 0..2 all RY/RZ (indices 0..47) + final RY(q0) (48)
        float p = 1.0f;
#pragma unroll
        for (int i = 0; i < 49; i++) p *= wcs[i];
        scale2 = p * p;
    }
    __syncthreads();

    const int lane = tid & 31;
    const int sample = blockIdx.x * 8 + (tid >> 5);   // one sample per warp

    // Composed inverse lane permutation for ring CNOTs i=0..3 (lane bits)
    const int b4 = (lane >> 4) & 1, b3 = (lane >> 3) & 1, b2 = (lane >> 2) & 1,
              b1 = (lane >> 1) & 1, b0 = lane & 1;
    const int src0123 = (b4 << 4) | ((b3 ^ b4) << 3) | ((b2 ^ b3) << 2) |
                        ((b1 ^ b2) << 1) | (b0 ^ b1);

    // ---------- Angle encoding as direct product state (all-real) ----------
    float cq[8], sq[8];
    {
        const float4* xv = (const float4*)(x + sample * NQ);
        float4 xa = __ldg(xv), xb = __ldg(xv + 1);
        float xs[8] = {xa.x, xa.y, xa.z, xa.w, xb.x, xb.y, xb.z, xb.w};
#pragma unroll
        for (int q = 0; q < 8; q++) __sincosf(0.5f * xs[q], &sq[q], &cq[q]);
    }
    float A = (b4 ? sq[0] : cq[0]) * (b3 ? sq[1] : cq[1]) * (b2 ? sq[2] : cq[2]) *
              (b1 ? sq[3] : cq[3]) * (b0 ? sq[4] : cq[4]);
    float u2[2], u4[4];
    u2[0] = A * cq[5];  u2[1] = A * sq[5];
#pragma unroll
    for (int k = 0; k < 4; k++) u4[k] = u2[k >> 1] * ((k & 1) ? sq[6] : cq[6]);

    float2 PR[4], PI[4];
#pragma unroll
    for (int k = 0; k < 4; k++) {
        PR[k] = make_float2(u4[k] * cq[7], u4[k] * sq[7]);
        PI[k] = make_float2(0.0f, 0.0f);
    }

    // ---------------- Layers 0..2: full ring + all rotations (tan form) ----
#pragma unroll 1
    for (int l = 0; l < NL - 1; l++) {
        cnot_ring(PR, PI, lane, src0123);
        const int lbase = l * 16;
#pragma unroll
        for (int i = 0; i < NQ; i++) {
            const float ty = wt[lbase + i * 2];
            const float tz = wt[lbase + i * 2 + 1];
            if (i < 5) {
                const int lb = 16 >> i;
                ry_ln_t(PR, PI, ty, lb, lane);
                rz_ln_t(PR, PI, tz, lb, lane);
            } else if (i == 7) {
                ry_pk_t(PR, PI, ty);
                rz_pk_t(PR, PI, tz);
            } else {
                const int ks = 1 << (6 - i);   // q5 -> 2, q6 -> 1
                ry_reg_t(PR, PI, ty, ks);
                rz_reg_t(PR, PI, tz, ks);
            }
        }
    }

    // ---------------- Layer 3: ring + RY(q0) only (tan form) ---------------
    // Other final-layer rotations act on qubits != q0 (preserve q0 marginal)
    // or are diagonal (preserve |amp|^2) -> no effect on <Z_0>.
    cnot_ring(PR, PI, lane, src0123);
    ry_ln_t(PR, PI, wt[3 * 16], 16, lane);

    // ---------------- <Z_0>: q0 = lane bit4, scaled by C^2 ----------------
    float2 a2 = make_float2(0.0f, 0.0f);
#pragma unroll
    for (int k = 0; k < 4; k++) {
        a2 = f2fma(PR[k], PR[k], a2);
        a2 = f2fma(PI[k], PI[k], a2);
    }
    float acc = a2.x + a2.y;
    if (lane & 16) acc = -acc;
    acc += __shfl_xor_sync(FULLMASK, acc, 1);
    acc += __shfl_xor_sync(FULLMASK, acc, 2);
    acc += __shfl_xor_sync(FULLMASK, acc, 4);
    acc += __shfl_xor_sync(FULLMASK, acc, 8);
    acc += __shfl_xor_sync(FULLMASK, acc, 16);
    if (lane == 0) out[sample] = acc * scale2;
}

extern "C" void kernel_launch(void* const* d_in, const int* in_sizes, int n_in,
                              void* d_out, int out_size) {
    const float* x = (const float*)d_in[0];   // (4096, 8)
    const float* w = (const float*)d_in[1];   // (4, 8, 2)
    float* out = (float*)d_out;               // (4096,)
    // 256 threads = 8 warps = 8 samples per block; 512 blocks, 4096 warps
    vqc_kernel<<<BATCHN / 8, 256>>>(x, w, out);
}